// round 3
// baseline (speedup 1.0000x reference)
#include <cuda_runtime.h>
#include <cstdint>

#define HH 8
#define BB 8
#define SS 4096
#define DD 64
#define DMOUT 768
#define SM1 (SS-2)            // 4094
#define NKROWS (BB*SM1)       // 32752
#define KTOT (HH*DD)          // 512

// ---------------- scratch (no allocs allowed) ----------------
static __device__ float dG[HH*DD*DD];     // Gram of normalized Q
static __device__ float dU[HH*DD*DD];     // Q^T V update
static __device__ float dNT[HH*DD*DD];    // new_trace
static __device__ float dM[KTOT*DMOUT];   // fused weight: nt @ W_out_h^T

// ---------------- helpers ----------------
__device__ __forceinline__ uint32_t f2tf(float x){
    uint32_t r; asm("cvt.rna.tf32.f32 %0, %1;" : "=r"(r) : "f"(x)); return r;
}
__device__ __forceinline__ void mma_tf32(float c[4], uint32_t a0,uint32_t a1,uint32_t a2,uint32_t a3,
                                         uint32_t b0,uint32_t b1){
    asm volatile("mma.sync.aligned.m16n8k8.row.col.f32.tf32.tf32.f32 "
        "{%0,%1,%2,%3},{%4,%5,%6,%7},{%8,%9},{%0,%1,%2,%3};"
        : "+f"(c[0]),"+f"(c[1]),"+f"(c[2]),"+f"(c[3])
        : "r"(a0),"r"(a1),"r"(a2),"r"(a3),"r"(b0),"r"(b1));
}

// ---------------- kernel 0: zero scratch ----------------
__global__ void k_zero(){
    int i = blockIdx.x*256 + threadIdx.x;   // 128 blocks -> 32768
    dG[i] = 0.f; dU[i] = 0.f;
}

// ---------------- kernel 1: G[h] = Qe^T Qe, U[h] = Q^T V ----------------
// grid (32 chunks, 8 heads), 128 threads (4 warps). Warp owns 16 M-rows x 64 N.
// Register-prefetched mainloop; norms via 4-thread shfl reduction.
__global__ void __launch_bounds__(128) k_stage1(const float* __restrict__ Q,
                                                const float* __restrict__ V){
    const int h    = blockIdx.y;
    const int row0 = blockIdx.x * 1024;
    const int tid  = threadIdx.x;
    const int warp = tid >> 5, lane = tid & 31;
    const int grp  = lane >> 2, tg = lane & 3;

    __shared__ float sQ[32][72];
    __shared__ float sV[32][72];
    __shared__ float sInv[32];     // 1/max(||q||,eps)^2 per row

    float accG[8][4], accU[8][4];
    #pragma unroll
    for(int i=0;i<8;i++){
        #pragma unroll
        for(int j=0;j<4;j++){ accG[i][j]=0.f; accU[i][j]=0.f; }
    }
    const int m0 = warp*16 + grp;

    // loader coords (fixed): 4 float4 per thread per tensor
    int lrow[4], lc4[4];
    #pragma unroll
    for(int j=0;j<4;j++){ int f4 = tid + j*128; lrow[j] = f4 >> 4; lc4[j] = f4 & 15; }

    float4 pq[4], pv[4];
    // prefetch tile 0
    #pragma unroll
    for(int j=0;j<4;j++){
        int gr = row0 + lrow[j];
        pq[j] = make_float4(0.f,0.f,0.f,0.f);
        pv[j] = make_float4(0.f,0.f,0.f,0.f);
        if(gr < NKROWS){
            int b = gr / SM1;
            int i = gr - b*SM1;
            size_t qoff = (((size_t)(b*HH + h))*SS + i)*DD;
            size_t voff = (((size_t)(b*HH + h))*SS + i + 2)*DD;
            pq[j] = *((const float4*)(Q + qoff) + lc4[j]);
            pv[j] = *((const float4*)(V + voff) + lc4[j]);
        }
    }

    for(int kt=0; kt<32; kt++){
        #pragma unroll
        for(int j=0;j<4;j++){
            *(float4*)&sQ[lrow[j]][lc4[j]*4] = pq[j];
            *(float4*)&sV[lrow[j]][lc4[j]*4] = pv[j];
        }
        __syncthreads();

        // norms: 4 threads per row, 16 elements each, shfl-reduce
        {
            const int row = tid >> 2, seg = tid & 3;
            float s = 0.f;
            #pragma unroll
            for(int i=0;i<4;i++){
                float4 x = *(float4*)&sQ[row][seg*16 + i*4];
                s += x.x*x.x + x.y*x.y + x.z*x.z + x.w*x.w;
            }
            s += __shfl_xor_sync(0xffffffffu, s, 1);
            s += __shfl_xor_sync(0xffffffffu, s, 2);
            if(seg == 0) sInv[row] = 1.f / fmaxf(s, 1e-16f);
        }
        __syncthreads();

        // prefetch next tile (overlaps MMA)
        if(kt < 31){
            const int base = row0 + (kt+1)*32;
            #pragma unroll
            for(int j=0;j<4;j++){
                int gr = base + lrow[j];
                pq[j] = make_float4(0.f,0.f,0.f,0.f);
                pv[j] = make_float4(0.f,0.f,0.f,0.f);
                if(gr < NKROWS){
                    int b = gr / SM1;
                    int i = gr - b*SM1;
                    size_t qoff = (((size_t)(b*HH + h))*SS + i)*DD;
                    size_t voff = (((size_t)(b*HH + h))*SS + i + 2)*DD;
                    pq[j] = *((const float4*)(Q + qoff) + lc4[j]);
                    pv[j] = *((const float4*)(V + voff) + lc4[j]);
                }
            }
        }

        #pragma unroll
        for(int ks=0; ks<4; ks++){
            const int kA = ks*8 + tg;
            float ar0 = sQ[kA  ][m0  ], ar1 = sQ[kA  ][m0+8];
            float ar2 = sQ[kA+4][m0  ], ar3 = sQ[kA+4][m0+8];
            float i0 = sInv[kA], i1 = sInv[kA+4];
            uint32_t aU0=f2tf(ar0),    aU1=f2tf(ar1),    aU2=f2tf(ar2),    aU3=f2tf(ar3);
            uint32_t aG0=f2tf(ar0*i0), aG1=f2tf(ar1*i0), aG2=f2tf(ar2*i1), aG3=f2tf(ar3*i1);
            #pragma unroll
            for(int nt=0; nt<8; nt++){
                const int n = nt*8 + grp;
                uint32_t bq0 = f2tf(sQ[kA  ][n]);
                uint32_t bq1 = f2tf(sQ[kA+4][n]);
                uint32_t bv0 = f2tf(sV[kA  ][n]);
                uint32_t bv1 = f2tf(sV[kA+4][n]);
                mma_tf32(accG[nt], aG0,aG1,aG2,aG3, bq0,bq1);
                mma_tf32(accU[nt], aU0,aU1,aU2,aU3, bv0,bv1);
            }
        }
        __syncthreads();
    }
    // reduce partials into global scratch
    #pragma unroll
    for(int nt=0; nt<8; nt++){
        const int n = nt*8 + tg*2;
        int baseIdx = h*4096;
        atomicAdd(&dG[baseIdx + (m0  )*64 + n  ], accG[nt][0]);
        atomicAdd(&dG[baseIdx + (m0  )*64 + n+1], accG[nt][1]);
        atomicAdd(&dG[baseIdx + (m0+8)*64 + n  ], accG[nt][2]);
        atomicAdd(&dG[baseIdx + (m0+8)*64 + n+1], accG[nt][3]);
        atomicAdd(&dU[baseIdx + (m0  )*64 + n  ], accU[nt][0]);
        atomicAdd(&dU[baseIdx + (m0  )*64 + n+1], accU[nt][1]);
        atomicAdd(&dU[baseIdx + (m0+8)*64 + n  ], accU[nt][2]);
        atomicAdd(&dU[baseIdx + (m0+8)*64 + n+1], accU[nt][3]);
    }
}

// ---------------- kernel 2: new_trace = 0.99*(trace - G@trace/denom) + 0.1*U/denom ----------------
// grid (4 p-chunks, 8 heads), 256 threads; float4 inner loop over q.
__global__ void __launch_bounds__(256) k_trace(const float* __restrict__ trace){
    const int h = blockIdx.y, p0 = blockIdx.x*16, tid = threadIdx.x;
    __shared__ float sT[4096];
    __shared__ float sG[16*64];
    #pragma unroll
    for(int t=0;t<16;t++){ int i = tid + t*256; sT[i] = trace[h*4096 + i]; }
    #pragma unroll
    for(int t=0;t<4;t++){ int i = tid + t*256; sG[i] = dG[h*4096 + p0*64 + i]; }
    __syncthreads();
    const float inv = 1.f/(float)NKROWS;
    const int pl = tid >> 4;            // 0..15
    const int q0 = (tid & 15) * 4;      // 0..60
    float4 gt = make_float4(0.f,0.f,0.f,0.f);
    #pragma unroll
    for(int r=0;r<64;r++){
        float g = sG[pl*64 + r];
        float4 t = *(float4*)&sT[r*64 + q0];
        gt.x += g*t.x; gt.y += g*t.y; gt.z += g*t.z; gt.w += g*t.w;
    }
    const int gi = h*4096 + (p0 + pl)*64 + q0;
    float4 tt = *(float4*)&sT[(p0+pl)*64 + q0];
    float4 uu = *(float4*)&dU[gi];
    float4 o;
    o.x = 0.99f*(tt.x - gt.x*inv) + 0.1f*uu.x*inv;
    o.y = 0.99f*(tt.y - gt.y*inv) + 0.1f*uu.y*inv;
    o.z = 0.99f*(tt.z - gt.z*inv) + 0.1f*uu.z*inv;
    o.w = 0.99f*(tt.w - gt.w*inv) + 0.1f*uu.w*inv;
    *(float4*)&dNT[gi] = o;
}

// ---------------- kernel 3: M[h*64+p][dm] = sum_q nt[h][p][q] * W_out[dm][h*64+q] ----------------
// grid (12 dm-chunks, 8 heads), 256 threads; float4 dot products.
__global__ void __launch_bounds__(256) k_makeM(const float* __restrict__ Wout){
    const int h = blockIdx.y;
    const int dm0 = blockIdx.x * 64;
    const int tid = threadIdx.x;
    __shared__ float sNT[4096];
    __shared__ float sW[64*68];     // stride 68 floats (16B-aligned rows)
    #pragma unroll
    for(int t=0;t<16;t++){ int i = tid + t*256; sNT[i] = dNT[h*4096 + i]; }
    #pragma unroll
    for(int t=0;t<16;t++){
        int i = tid + t*256; int r = i >> 6, q = i & 63;
        sW[r*68 + q] = Wout[(size_t)(dm0 + r)*KTOT + h*64 + q];
    }
    __syncthreads();
    #pragma unroll
    for(int t=0;t<16;t++){
        int i = tid + t*256; int p = i >> 6, dm = i & 63;
        const float4* a4 = (const float4*)&sNT[p*64];
        const float4* w4 = (const float4*)&sW[dm*68];
        float s = 0.f;
        #pragma unroll
        for(int q=0;q<16;q++){
            float4 a = a4[q], w = w4[q];
            s += a.x*w.x + a.y*w.y + a.z*w.z + a.w*w.w;
        }
        dM[(size_t)(h*64 + p)*DMOUT + dm0 + dm] = s;
    }
}

// ---------------- kernel 4: fused out = X @ M,  X[b*S+s][:] = Q[b,:,s-1,:] (0 at s=0) ----------------
// grid (6 n-tiles, 256 m-tiles), 256 threads = 8 warps (2M x 4N), warp tile 64x32, BK=32.
// Fragment-packed smem: A frag = one LDS.128, B frag pair = one LDS.64.
__global__ void __launch_bounds__(256) k_gemm(const float* __restrict__ Q,
                                              float* __restrict__ out){
    const int nblk = blockIdx.x;
    const int mblk = blockIdx.y;
    const int tid  = threadIdx.x;
    const int warp = tid >> 5, lane = tid & 31;
    const int grp  = lane >> 2, tg = lane & 3;
    const int warpM = warp >> 2, warpN = warp & 3;

    // A packed: idx = ((mrow16*4 + ks)*32 + lane)*4 + slot, slot = khi*2 + hi
    __shared__ float sA[4096];
    // B packed: idx = ks*1024 + n*8 + tg*2 + khi
    __shared__ float sB[4096];

    float acc[4][4][4];
    #pragma unroll
    for(int mi=0;mi<4;mi++)
        #pragma unroll
        for(int ni=0;ni<4;ni++)
            #pragma unroll
            for(int f=0;f<4;f++) acc[mi][ni][f] = 0.f;

    const int r0  = mblk*128;
    const int b   = r0 >> 12;       // tiles never straddle a batch
    const int s0  = r0 & 4095;
    const int n0g = nblk*128;

    // loader coords + tile-invariant smem store bases
    int arow[4], ac4[4], brow[4], bc4[4];
    int aBase[4], bBase[4];
    #pragma unroll
    for(int j=0;j<4;j++){
        int f4 = tid + j*256;
        arow[j] = f4 >> 3; ac4[j] = f4 & 7;    // A: 128 rows x 8 float4
        brow[j] = f4 >> 5; bc4[j] = f4 & 31;   // B: 32 rows x 32 float4
        // A store base (element e adds 4 floats)
        aBase[j] = (((arow[j]>>4)*4 + (ac4[j]>>1))*32 + (arow[j]&7)*4)*4
                   + (ac4[j]&1)*2 + ((arow[j]>>3)&1);
        // B store base (element e adds 8 floats)
        bBase[j] = (brow[j]>>3)*1024 + bc4[j]*32 + (brow[j]&3)*2 + ((brow[j]>>2)&1);
    }

    float4 pa[4], pb[4];
    // prefetch k-tile 0
    {
        const float* Qbase = Q + ((size_t)(b*HH))*SS*DD;
        #pragma unroll
        for(int j=0;j<4;j++){
            int s = s0 + arow[j];
            pa[j] = make_float4(0.f,0.f,0.f,0.f);
            if(s > 0)
                pa[j] = *((const float4*)(Qbase + (size_t)(s-1)*DD) + ac4[j]);
            pb[j] = *((const float4*)(dM + (size_t)brow[j]*DMOUT + n0g) + bc4[j]);
        }
    }

    // consumer addresses (tile-invariant)
    int aAddr[4];   // per mi: float index of the LDS.128 (varies with ks by +32*4)
    #pragma unroll
    for(int mi=0;mi<4;mi++)
        aAddr[mi] = (((warpM*4 + mi)*4)*32 + lane)*4;
    int bAddr[4];   // per ni: float index of the LDS.64 (varies with ks by +1024)
    #pragma unroll
    for(int ni=0;ni<4;ni++)
        bAddr[ni] = (warpN*32 + ni*8 + grp)*8 + tg*2;

    for(int kb=0; kb<16; kb++){
        // scatter prefetched tile into packed smem (tf32-converted)
        #pragma unroll
        for(int j=0;j<4;j++){
            float* da = &sA[aBase[j]];
            da[0]  = __uint_as_float(f2tf(pa[j].x));
            da[4]  = __uint_as_float(f2tf(pa[j].y));
            da[8]  = __uint_as_float(f2tf(pa[j].z));
            da[12] = __uint_as_float(f2tf(pa[j].w));
            float* db = &sB[bBase[j]];
            db[0]  = __uint_as_float(f2tf(pb[j].x));
            db[8]  = __uint_as_float(f2tf(pb[j].y));
            db[16] = __uint_as_float(f2tf(pb[j].z));
            db[24] = __uint_as_float(f2tf(pb[j].w));
        }
        __syncthreads();

        // prefetch next k-tile (overlaps MMA)
        if(kb < 15){
            const int k0 = (kb+1)*32;
            const int hh = k0 >> 6;
            const int d0 = k0 & 63;
            const float* Qbase = Q + ((size_t)(b*HH + hh))*SS*DD;
            #pragma unroll
            for(int j=0;j<4;j++){
                int s = s0 + arow[j];
                pa[j] = make_float4(0.f,0.f,0.f,0.f);
                if(s > 0)
                    pa[j] = *((const float4*)(Qbase + (size_t)(s-1)*DD + d0) + ac4[j]);
                pb[j] = *((const float4*)(dM + (size_t)(k0 + brow[j])*DMOUT + n0g) + bc4[j]);
            }
        }

        #pragma unroll
        for(int ks=0; ks<4; ks++){
            float4 af[4];
            #pragma unroll
            for(int mi=0;mi<4;mi++)
                af[mi] = *(const float4*)&sA[aAddr[mi] + ks*128];
            #pragma unroll
            for(int ni=0;ni<4;ni++){
                float2 bf = *(const float2*)&sB[bAddr[ni] + ks*1024];
                uint32_t b0 = __float_as_uint(bf.x);
                uint32_t b1 = __float_as_uint(bf.y);
                #pragma unroll
                for(int mi=0;mi<4;mi++)
                    mma_tf32(acc[mi][ni],
                             __float_as_uint(af[mi].x), __float_as_uint(af[mi].y),
                             __float_as_uint(af[mi].z), __float_as_uint(af[mi].w),
                             b0, b1);
            }
        }
        __syncthreads();
    }

    // epilogue
    #pragma unroll
    for(int mi=0;mi<4;mi++){
        const int m = warpM*64 + mi*16 + grp;
        const size_t r1 = (size_t)(r0 + m    )*DMOUT;
        const size_t r2 = (size_t)(r0 + m + 8)*DMOUT;
        #pragma unroll
        for(int ni=0;ni<4;ni++){
            const int n = n0g + warpN*32 + ni*8 + tg*2;
            *(float2*)&out[r1 + n] = make_float2(acc[mi][ni][0], acc[mi][ni][1]);
            *(float2*)&out[r2 + n] = make_float2(acc[mi][ni][2], acc[mi][ni][3]);
        }
    }
}

// ---------------- launch ----------------
extern "C" void kernel_launch(void* const* d_in, const int* in_sizes, int n_in,
                              void* d_out, int out_size){
    const float* Q     = (const float*)d_in[0];
    const float* V     = (const float*)d_in[1];
    const float* trace = (const float*)d_in[2];
    const float* Wout  = (const float*)d_in[3];
    float* out = (float*)d_out;

    k_zero<<<128, 256>>>();
    dim3 g1(32, HH);  k_stage1<<<g1, 128>>>(Q, V);
    dim3 g2(4, HH);   k_trace<<<g2, 256>>>(trace);
    dim3 g3(12, HH);  k_makeM<<<g3, 256>>>(Wout);
    dim3 g4(6, 256);  k_gemm<<<g4, 256>>>(Q, out);
}

// round 4
// speedup vs baseline: 2.5596x; 2.5596x over previous
#include <cuda_runtime.h>
#include <cstdint>

#define HH 8
#define BB 8
#define SS 4096
#define DD 64
#define DMOUT 768
#define SM1 (SS-2)            // 4094
#define NKROWS (BB*SM1)       // 32752
#define KTOT (HH*DD)          // 512

// ---------------- scratch (no allocs allowed) ----------------
static __device__ float dG[HH*DD*DD];     // Gram of normalized Q
static __device__ float dU[HH*DD*DD];     // Q^T V update
static __device__ float dNT[HH*DD*DD];    // new_trace
static __device__ float dM[KTOT*DMOUT];   // fused weight: nt @ W_out_h^T (pre-rounded tf32)

// ---------------- helpers ----------------
__device__ __forceinline__ uint32_t f2tf(float x){
    uint32_t r; asm("cvt.rna.tf32.f32 %0, %1;" : "=r"(r) : "f"(x)); return r;
}
__device__ __forceinline__ void mma_tf32(float c[4], uint32_t a0,uint32_t a1,uint32_t a2,uint32_t a3,
                                         uint32_t b0,uint32_t b1){
    asm volatile("mma.sync.aligned.m16n8k8.row.col.f32.tf32.tf32.f32 "
        "{%0,%1,%2,%3},{%4,%5,%6,%7},{%8,%9},{%0,%1,%2,%3};"
        : "+f"(c[0]),"+f"(c[1]),"+f"(c[2]),"+f"(c[3])
        : "r"(a0),"r"(a1),"r"(a2),"r"(a3),"r"(b0),"r"(b1));
}

// ---------------- kernel 0: zero scratch ----------------
__global__ void k_zero(){
    int i = blockIdx.x*256 + threadIdx.x;   // 128 blocks -> 32768
    dG[i] = 0.f; dU[i] = 0.f;
}

// ---------------- kernel 1: G[h] = Qe^T Qe, U[h] = Q^T V ----------------
// grid (32 chunks, 8 heads), 128 threads (4 warps). Warp owns 16 M-rows x 64 N.
// Register-prefetched mainloop; norms via 4-thread shfl reduction.
__global__ void __launch_bounds__(128) k_stage1(const float* __restrict__ Q,
                                                const float* __restrict__ V){
    const int h    = blockIdx.y;
    const int row0 = blockIdx.x * 1024;
    const int tid  = threadIdx.x;
    const int warp = tid >> 5, lane = tid & 31;
    const int grp  = lane >> 2, tg = lane & 3;

    __shared__ float sQ[32][72];
    __shared__ float sV[32][72];
    __shared__ float sInv[32];     // 1/max(||q||,eps)^2 per row

    float accG[8][4], accU[8][4];
    #pragma unroll
    for(int i=0;i<8;i++){
        #pragma unroll
        for(int j=0;j<4;j++){ accG[i][j]=0.f; accU[i][j]=0.f; }
    }
    const int m0 = warp*16 + grp;

    int lrow[4], lc4[4];
    #pragma unroll
    for(int j=0;j<4;j++){ int f4 = tid + j*128; lrow[j] = f4 >> 4; lc4[j] = f4 & 15; }

    float4 pq[4], pv[4];
    #pragma unroll
    for(int j=0;j<4;j++){
        int gr = row0 + lrow[j];
        pq[j] = make_float4(0.f,0.f,0.f,0.f);
        pv[j] = make_float4(0.f,0.f,0.f,0.f);
        if(gr < NKROWS){
            int b = gr / SM1;
            int i = gr - b*SM1;
            size_t qoff = (((size_t)(b*HH + h))*SS + i)*DD;
            size_t voff = (((size_t)(b*HH + h))*SS + i + 2)*DD;
            pq[j] = *((const float4*)(Q + qoff) + lc4[j]);
            pv[j] = *((const float4*)(V + voff) + lc4[j]);
        }
    }

    for(int kt=0; kt<32; kt++){
        #pragma unroll
        for(int j=0;j<4;j++){
            *(float4*)&sQ[lrow[j]][lc4[j]*4] = pq[j];
            *(float4*)&sV[lrow[j]][lc4[j]*4] = pv[j];
        }
        __syncthreads();

        {
            const int row = tid >> 2, seg = tid & 3;
            float s = 0.f;
            #pragma unroll
            for(int i=0;i<4;i++){
                float4 x = *(float4*)&sQ[row][seg*16 + i*4];
                s += x.x*x.x + x.y*x.y + x.z*x.z + x.w*x.w;
            }
            s += __shfl_xor_sync(0xffffffffu, s, 1);
            s += __shfl_xor_sync(0xffffffffu, s, 2);
            if(seg == 0) sInv[row] = 1.f / fmaxf(s, 1e-16f);
        }
        __syncthreads();

        if(kt < 31){
            const int base = row0 + (kt+1)*32;
            #pragma unroll
            for(int j=0;j<4;j++){
                int gr = base + lrow[j];
                pq[j] = make_float4(0.f,0.f,0.f,0.f);
                pv[j] = make_float4(0.f,0.f,0.f,0.f);
                if(gr < NKROWS){
                    int b = gr / SM1;
                    int i = gr - b*SM1;
                    size_t qoff = (((size_t)(b*HH + h))*SS + i)*DD;
                    size_t voff = (((size_t)(b*HH + h))*SS + i + 2)*DD;
                    pq[j] = *((const float4*)(Q + qoff) + lc4[j]);
                    pv[j] = *((const float4*)(V + voff) + lc4[j]);
                }
            }
        }

        #pragma unroll
        for(int ks=0; ks<4; ks++){
            const int kA = ks*8 + tg;
            float ar0 = sQ[kA  ][m0  ], ar1 = sQ[kA  ][m0+8];
            float ar2 = sQ[kA+4][m0  ], ar3 = sQ[kA+4][m0+8];
            float i0 = sInv[kA], i1 = sInv[kA+4];
            uint32_t aU0=f2tf(ar0),    aU1=f2tf(ar1),    aU2=f2tf(ar2),    aU3=f2tf(ar3);
            uint32_t aG0=f2tf(ar0*i0), aG1=f2tf(ar1*i0), aG2=f2tf(ar2*i1), aG3=f2tf(ar3*i1);
            #pragma unroll
            for(int nt=0; nt<8; nt++){
                const int n = nt*8 + grp;
                uint32_t bq0 = f2tf(sQ[kA  ][n]);
                uint32_t bq1 = f2tf(sQ[kA+4][n]);
                uint32_t bv0 = f2tf(sV[kA  ][n]);
                uint32_t bv1 = f2tf(sV[kA+4][n]);
                mma_tf32(accG[nt], aG0,aG1,aG2,aG3, bq0,bq1);
                mma_tf32(accU[nt], aU0,aU1,aU2,aU3, bv0,bv1);
            }
        }
        __syncthreads();
    }
    #pragma unroll
    for(int nt=0; nt<8; nt++){
        const int n = nt*8 + tg*2;
        int baseIdx = h*4096;
        atomicAdd(&dG[baseIdx + (m0  )*64 + n  ], accG[nt][0]);
        atomicAdd(&dG[baseIdx + (m0  )*64 + n+1], accG[nt][1]);
        atomicAdd(&dG[baseIdx + (m0+8)*64 + n  ], accG[nt][2]);
        atomicAdd(&dG[baseIdx + (m0+8)*64 + n+1], accG[nt][3]);
        atomicAdd(&dU[baseIdx + (m0  )*64 + n  ], accU[nt][0]);
        atomicAdd(&dU[baseIdx + (m0  )*64 + n+1], accU[nt][1]);
        atomicAdd(&dU[baseIdx + (m0+8)*64 + n  ], accU[nt][2]);
        atomicAdd(&dU[baseIdx + (m0+8)*64 + n+1], accU[nt][3]);
    }
}

// ---------------- kernel 2: new_trace = 0.99*(trace - G@trace/denom) + 0.1*U/denom ----------------
__global__ void __launch_bounds__(256) k_trace(const float* __restrict__ trace){
    const int h = blockIdx.y, p0 = blockIdx.x*16, tid = threadIdx.x;
    __shared__ float sT[4096];
    __shared__ float sG[16*64];
    #pragma unroll
    for(int t=0;t<16;t++){ int i = tid + t*256; sT[i] = trace[h*4096 + i]; }
    #pragma unroll
    for(int t=0;t<4;t++){ int i = tid + t*256; sG[i] = dG[h*4096 + p0*64 + i]; }
    __syncthreads();
    const float inv = 1.f/(float)NKROWS;
    const int pl = tid >> 4;
    const int q0 = (tid & 15) * 4;
    float4 gt = make_float4(0.f,0.f,0.f,0.f);
    #pragma unroll
    for(int r=0;r<64;r++){
        float g = sG[pl*64 + r];
        float4 t = *(float4*)&sT[r*64 + q0];
        gt.x += g*t.x; gt.y += g*t.y; gt.z += g*t.z; gt.w += g*t.w;
    }
    const int gi = h*4096 + (p0 + pl)*64 + q0;
    float4 tt = *(float4*)&sT[(p0+pl)*64 + q0];
    float4 uu = *(float4*)&dU[gi];
    float4 o;
    o.x = 0.99f*(tt.x - gt.x*inv) + 0.1f*uu.x*inv;
    o.y = 0.99f*(tt.y - gt.y*inv) + 0.1f*uu.y*inv;
    o.z = 0.99f*(tt.z - gt.z*inv) + 0.1f*uu.z*inv;
    o.w = 0.99f*(tt.w - gt.w*inv) + 0.1f*uu.w*inv;
    *(float4*)&dNT[gi] = o;
}

// ---------------- kernel 3: M = nt @ W_h^T, stored pre-rounded to tf32 ----------------
__global__ void __launch_bounds__(256) k_makeM(const float* __restrict__ Wout){
    const int h = blockIdx.y;
    const int dm0 = blockIdx.x * 64;
    const int tid = threadIdx.x;
    __shared__ float sNT[4096];
    __shared__ float sW[64*68];
    #pragma unroll
    for(int t=0;t<16;t++){ int i = tid + t*256; sNT[i] = dNT[h*4096 + i]; }
    #pragma unroll
    for(int t=0;t<16;t++){
        int i = tid + t*256; int r = i >> 6, q = i & 63;
        sW[r*68 + q] = Wout[(size_t)(dm0 + r)*KTOT + h*64 + q];
    }
    __syncthreads();
    #pragma unroll
    for(int t=0;t<16;t++){
        int i = tid + t*256; int p = i >> 6, dm = i & 63;
        const float4* a4 = (const float4*)&sNT[p*64];
        const float4* w4 = (const float4*)&sW[dm*68];
        float s = 0.f;
        #pragma unroll
        for(int q=0;q<16;q++){
            float4 a = a4[q], w = w4[q];
            s += a.x*w.x + a.y*w.y + a.z*w.z + a.w*w.w;
        }
        dM[(size_t)(h*64 + p)*DMOUT + dm0 + dm] = __uint_as_float(f2tf(s));
    }
}

// ---------------- kernel 4: fused out = X @ M,  X[b*S+s][:] = Q[b,:,s-1,:] (0 at s=0) ----------------
// grid (6 n-tiles, 256 m-tiles), 256 threads = 8 warps (2M x 4N), warp tile 64x32, BK=32.
// Double-buffered smem, one __syncthreads per k-tile; B pre-rounded to tf32 in k_makeM.
__global__ void __launch_bounds__(256) k_gemm(const float* __restrict__ Q,
                                              float* __restrict__ out){
    const int nblk = blockIdx.x;
    const int mblk = blockIdx.y;
    const int tid  = threadIdx.x;
    const int warp = tid >> 5, lane = tid & 31;
    const int grp  = lane >> 2, tg = lane & 3;
    const int warpM = warp >> 2, warpN = warp & 3;

    __shared__ float sA[2][128*36];   // [m][k], stride 36
    __shared__ float sB[2][32*136];   // [k][n], stride 136

    float acc[4][4][4];
    #pragma unroll
    for(int mi=0;mi<4;mi++)
        #pragma unroll
        for(int ni=0;ni<4;ni++)
            #pragma unroll
            for(int f=0;f<4;f++) acc[mi][ni][f] = 0.f;

    const int r0  = mblk*128;
    const int b   = r0 >> 12;       // tiles never straddle a batch
    const int s0  = r0 & 4095;
    const int n0g = nblk*128;

    int arow[4], ac4[4], brow[4], bc4[4];
    #pragma unroll
    for(int j=0;j<4;j++){
        int f4 = tid + j*256;
        arow[j] = f4 >> 3; ac4[j] = f4 & 7;    // A: 128 rows x 8 float4
        brow[j] = f4 >> 5; bc4[j] = f4 & 31;   // B: 32 rows x 32 float4
    }

    float4 pa[4], pb[4];
    // prefetch k-tile 0
    {
        const float* Qbase = Q + ((size_t)(b*HH))*SS*DD;
        #pragma unroll
        for(int j=0;j<4;j++){
            int s = s0 + arow[j];
            pa[j] = make_float4(0.f,0.f,0.f,0.f);
            if(s > 0)
                pa[j] = *((const float4*)(Qbase + (size_t)(s-1)*DD) + ac4[j]);
            pb[j] = *((const float4*)(dM + (size_t)brow[j]*DMOUT + n0g) + bc4[j]);
        }
    }

    for(int kb=0; kb<16; kb++){
        float* cA = sA[kb & 1];
        float* cB = sB[kb & 1];
        // store prefetched tile to smem (A tf32-converted; B already tf32)
        #pragma unroll
        for(int j=0;j<4;j++){
            float4 v = pa[j];
            v.x = __uint_as_float(f2tf(v.x));
            v.y = __uint_as_float(f2tf(v.y));
            v.z = __uint_as_float(f2tf(v.z));
            v.w = __uint_as_float(f2tf(v.w));
            *(float4*)&cA[arow[j]*36 + ac4[j]*4] = v;
            *(float4*)&cB[brow[j]*136 + bc4[j]*4] = pb[j];
        }
        __syncthreads();

        // prefetch next k-tile (overlaps MMA; lands in the other buffer next iter)
        if(kb < 15){
            const int k0 = (kb+1)*32;
            const int hh = k0 >> 6;
            const int d0 = k0 & 63;
            const float* Qbase = Q + ((size_t)(b*HH + hh))*SS*DD;
            #pragma unroll
            for(int j=0;j<4;j++){
                int s = s0 + arow[j];
                pa[j] = make_float4(0.f,0.f,0.f,0.f);
                if(s > 0)
                    pa[j] = *((const float4*)(Qbase + (size_t)(s-1)*DD + d0) + ac4[j]);
                pb[j] = *((const float4*)(dM + (size_t)(k0 + brow[j])*DMOUT + n0g) + bc4[j]);
            }
        }

        #pragma unroll
        for(int ks=0; ks<4; ks++){
            const int kk = ks*8 + tg;
            uint32_t a[4][4];
            #pragma unroll
            for(int mi=0;mi<4;mi++){
                int m = warpM*64 + mi*16 + grp;
                a[mi][0] = __float_as_uint(cA[(m  )*36 + kk  ]);
                a[mi][1] = __float_as_uint(cA[(m+8)*36 + kk  ]);
                a[mi][2] = __float_as_uint(cA[(m  )*36 + kk+4]);
                a[mi][3] = __float_as_uint(cA[(m+8)*36 + kk+4]);
            }
            #pragma unroll
            for(int ni=0;ni<4;ni++){
                int n = warpN*32 + ni*8 + grp;
                uint32_t b0 = __float_as_uint(cB[(kk  )*136 + n]);
                uint32_t b1 = __float_as_uint(cB[(kk+4)*136 + n]);
                #pragma unroll
                for(int mi=0;mi<4;mi++)
                    mma_tf32(acc[mi][ni], a[mi][0],a[mi][1],a[mi][2],a[mi][3], b0,b1);
            }
        }
        // no trailing sync: next iteration writes the other buffer; the next
        // __syncthreads orders all warps past this tile's MMAs before reuse.
    }

    // epilogue
    #pragma unroll
    for(int mi=0;mi<4;mi++){
        const int m = warpM*64 + mi*16 + grp;
        const size_t r1 = (size_t)(r0 + m    )*DMOUT;
        const size_t r2 = (size_t)(r0 + m + 8)*DMOUT;
        #pragma unroll
        for(int ni=0;ni<4;ni++){
            const int n = n0g + warpN*32 + ni*8 + tg*2;
            *(float2*)&out[r1 + n] = make_float2(acc[mi][ni][0], acc[mi][ni][1]);
            *(float2*)&out[r2 + n] = make_float2(acc[mi][ni][2], acc[mi][ni][3]);
        }
    }
}

// ---------------- launch ----------------
extern "C" void kernel_launch(void* const* d_in, const int* in_sizes, int n_in,
                              void* d_out, int out_size){
    const float* Q     = (const float*)d_in[0];
    const float* V     = (const float*)d_in[1];
    const float* trace = (const float*)d_in[2];
    const float* Wout  = (const float*)d_in[3];
    float* out = (float*)d_out;

    k_zero<<<128, 256>>>();
    dim3 g1(32, HH);  k_stage1<<<g1, 128>>>(Q, V);
    dim3 g2(4, HH);   k_trace<<<g2, 256>>>(trace);
    dim3 g3(12, HH);  k_makeM<<<g3, 256>>>(Wout);
    dim3 g4(6, 256);  k_gemm<<<g4, 256>>>(Q, out);
}